// round 4
// baseline (speedup 1.0000x reference)
#include <cuda_runtime.h>
#include <cuda_bf16.h>

// Sparsemax over rows: x, mask are [8192, 4096] fp32; out fp32 same shape.
// z = (mask ? x : NEG_BIG) * 2 ; tau solves sum(relu(z - tau)) = 1 (Newton);
// out = relu(z - tau)  (mask multiply implied: masked z is hugely negative).
//
// R4: persistent grid + one-row software pipeline. Next row's 16 KB of loads
// are issued BEFORE the current row's Newton/store phase, so the DRAM queue
// stays full through the compute phase. Single wave (no wave-transition dead
// time).

#define ROWS 8192
#define COLS 4096
#define THREADS 256
#define NWARPS (THREADS / 32)
#define ELEMS (COLS / THREADS)   // 16 floats per thread
#define VEC (ELEMS / 4)          // 4 float4 per thread
#define GRID 608                 // ~4 CTAs/SM persistent

__global__ __launch_bounds__(THREADS, 4)
void sparsemax_kernel(const float* __restrict__ x,
                      const float* __restrict__ m,
                      float* __restrict__ out) {
    const int t    = threadIdx.x;
    const int lane = t & 31;
    const int wid  = t >> 5;

    __shared__ float sh[2 * NWARPS];

    const float NEGZ = -9999999.9f * 2.0f;  // masked value after temperature

    int row = blockIdx.x;

    // ---- Prologue: stage first row's loads ----
    float4 xv[VEC];
    float4 mv[VEC];
    {
        const float4* xr = reinterpret_cast<const float4*>(x + (size_t)row * COLS);
        const float4* mr = reinterpret_cast<const float4*>(m + (size_t)row * COLS);
#pragma unroll
        for (int v = 0; v < VEC; v++) xv[v] = xr[t + v * THREADS];
#pragma unroll
        for (int v = 0; v < VEC; v++) mv[v] = mr[t + v * THREADS];
    }

#pragma unroll 1
    for (; row < ROWS; row += GRID) {
        // ---- Consume staged loads: mask + temperature, local max ----
        float z[ELEMS];
        float vmax = -3.0e38f;
#pragma unroll
        for (int v = 0; v < VEC; v++) {
            float z0 = (mv[v].x != 0.0f) ? (xv[v].x * 2.0f) : NEGZ;
            float z1 = (mv[v].y != 0.0f) ? (xv[v].y * 2.0f) : NEGZ;
            float z2 = (mv[v].z != 0.0f) ? (xv[v].z * 2.0f) : NEGZ;
            float z3 = (mv[v].w != 0.0f) ? (xv[v].w * 2.0f) : NEGZ;
            z[v * 4 + 0] = z0;
            z[v * 4 + 1] = z1;
            z[v * 4 + 2] = z2;
            z[v * 4 + 3] = z3;
            vmax = fmaxf(vmax, fmaxf(fmaxf(z0, z1), fmaxf(z2, z3)));
        }

        // ---- Prefetch next row NOW (covers Newton + store phase) ----
        const int nrow = row + GRID;
        if (nrow < ROWS) {
            const float4* xr = reinterpret_cast<const float4*>(x + (size_t)nrow * COLS);
            const float4* mr = reinterpret_cast<const float4*>(m + (size_t)nrow * COLS);
#pragma unroll
            for (int v = 0; v < VEC; v++) xv[v] = xr[t + v * THREADS];
#pragma unroll
            for (int v = 0; v < VEC; v++) mv[v] = mr[t + v * THREADS];
        }

        // ---- Block max reduction ----
#pragma unroll
        for (int o = 16; o > 0; o >>= 1)
            vmax = fmaxf(vmax, __shfl_xor_sync(0xFFFFFFFFu, vmax, o));
        if (lane == 0) sh[wid] = vmax;
        __syncthreads();
        float zmax = -3.0e38f;
#pragma unroll
        for (int i = 0; i < NWARPS; i++) zmax = fmaxf(zmax, sh[i]);
        __syncthreads();

        // ---- Newton on f(T) = sum(relu(z - T)) - 1, from the left ----
        float T = zmax - 1.0f;
#pragma unroll 1
        for (int it = 0; it < 32; ++it) {
            float s = 0.0f, c = 0.0f;
#pragma unroll
            for (int e = 0; e < ELEMS; e++) {
                float d = z[e] - T;
                if (d > 0.0f) { s += d; c += 1.0f; }
            }
#pragma unroll
            for (int o = 16; o > 0; o >>= 1) {
                s += __shfl_xor_sync(0xFFFFFFFFu, s, o);
                c += __shfl_xor_sync(0xFFFFFFFFu, c, o);
            }
            if (lane == 0) { sh[wid] = s; sh[NWARPS + wid] = c; }
            __syncthreads();
            float S = 0.0f, C = 0.0f;
#pragma unroll
            for (int i = 0; i < NWARPS; i++) { S += sh[i]; C += sh[NWARPS + i]; }
            __syncthreads();

            if (C < 0.5f) break;              // degenerate guard
            float delta = (S - 1.0f) / C;
            T += delta;
            if (fabsf(delta) < 1e-6f) break;  // uniform across block
        }

        // ---- Output: relu(z - T). Masked entries -> 0. ----
        float4* orow = reinterpret_cast<float4*>(out + (size_t)row * COLS);
#pragma unroll
        for (int v = 0; v < VEC; v++) {
            float4 ov;
            ov.x = fmaxf(0.0f, z[v * 4 + 0] - T);
            ov.y = fmaxf(0.0f, z[v * 4 + 1] - T);
            ov.z = fmaxf(0.0f, z[v * 4 + 2] - T);
            ov.w = fmaxf(0.0f, z[v * 4 + 3] - T);
            orow[t + v * THREADS] = ov;
        }
    }
}

extern "C" void kernel_launch(void* const* d_in, const int* in_sizes, int n_in,
                              void* d_out, int out_size) {
    const float* x = (const float*)d_in[0];
    const float* m = (const float*)d_in[1];
    float* out = (float*)d_out;
    sparsemax_kernel<<<GRID, THREADS>>>(x, m, out);
}

// round 5
// speedup vs baseline: 1.0619x; 1.0619x over previous
#include <cuda_runtime.h>
#include <cuda_bf16.h>

// Sparsemax over rows: x, mask are [8192, 4096] fp32; out fp32 same shape.
// z = (mask ? x : NEG_BIG) * 2 ; tau solves sum(relu(z - tau)) = 1 (Newton);
// out = relu(z - tau)  (mask multiply implied: masked z is hugely negative).
//
// R5 = R3 structure (best measured: front-batched loads, default cache
// policy, one row per CTA) + double-buffered reduction scratch so each
// Newton iteration costs ONE __syncthreads instead of two.

#define ROWS 8192
#define COLS 4096
#define THREADS 256
#define NWARPS (THREADS / 32)
#define ELEMS (COLS / THREADS)   // 16 floats per thread
#define VEC (ELEMS / 4)          // 4 float4 per thread

__global__ __launch_bounds__(THREADS, 5)
void sparsemax_kernel(const float* __restrict__ x,
                      const float* __restrict__ m,
                      float* __restrict__ out) {
    const int row = blockIdx.x;
    const int t   = threadIdx.x;
    const int lane = t & 31;
    const int wid  = t >> 5;

    const float4* __restrict__ xr = reinterpret_cast<const float4*>(x + (size_t)row * COLS);
    const float4* __restrict__ mr = reinterpret_cast<const float4*>(m + (size_t)row * COLS);
    float4* __restrict__ orow     = reinterpret_cast<float4*>(out + (size_t)row * COLS);

    // Double-buffered reduction scratch: buffer b holds (s[8], c[8]).
    __shared__ float sh[2][2 * NWARPS];

    // ---- Front-batch ALL loads (8 x LDG.128 in flight per thread) ----
    float4 xv[VEC];
    float4 mv[VEC];
#pragma unroll
    for (int v = 0; v < VEC; v++) xv[v] = xr[t + v * THREADS];
#pragma unroll
    for (int v = 0; v < VEC; v++) mv[v] = mr[t + v * THREADS];

    // ---- Apply mask + temperature, track local max ----
    float z[ELEMS];
    float vmax = -3.0e38f;
    const float NEGZ = -9999999.9f * 2.0f;  // masked value after temperature
#pragma unroll
    for (int v = 0; v < VEC; v++) {
        float z0 = (mv[v].x != 0.0f) ? (xv[v].x * 2.0f) : NEGZ;
        float z1 = (mv[v].y != 0.0f) ? (xv[v].y * 2.0f) : NEGZ;
        float z2 = (mv[v].z != 0.0f) ? (xv[v].z * 2.0f) : NEGZ;
        float z3 = (mv[v].w != 0.0f) ? (xv[v].w * 2.0f) : NEGZ;
        z[v * 4 + 0] = z0;
        z[v * 4 + 1] = z1;
        z[v * 4 + 2] = z2;
        z[v * 4 + 3] = z3;
        vmax = fmaxf(vmax, fmaxf(fmaxf(z0, z1), fmaxf(z2, z3)));
    }

    // ---- Block max reduction (uses buffer 0, consumed before iter 0 writes
    //      to buffer 0's slots -> needs its own barrier pair collapsed to 1:
    //      write -> bar -> read; iter 0 then writes buffer 1.) ----
#pragma unroll
    for (int o = 16; o > 0; o >>= 1)
        vmax = fmaxf(vmax, __shfl_xor_sync(0xFFFFFFFFu, vmax, o));
    if (lane == 0) sh[0][wid] = vmax;
    __syncthreads();
    float zmax = -3.0e38f;
#pragma unroll
    for (int i = 0; i < NWARPS; i++) zmax = fmaxf(zmax, sh[0][i]);
    // No trailing barrier: iteration 0 writes sh[1], not sh[0].

    // ---- Newton on f(T) = sum(relu(z - T)) - 1, from the left ----
    // T0 = zmax - 1 guarantees f(T0) >= 0; Newton from the left is monotone
    // increasing on convex piecewise-linear f and terminates exactly.
    float T = zmax - 1.0f;
#pragma unroll 1
    for (int it = 0; it < 32; ++it) {
        const int b = (it & 1) ^ 1;   // iter 0 -> buffer 1, iter 1 -> buffer 0, ...
        float s = 0.0f, c = 0.0f;
#pragma unroll
        for (int e = 0; e < ELEMS; e++) {
            float d = z[e] - T;
            if (d > 0.0f) { s += d; c += 1.0f; }
        }
#pragma unroll
        for (int o = 16; o > 0; o >>= 1) {
            s += __shfl_xor_sync(0xFFFFFFFFu, s, o);
            c += __shfl_xor_sync(0xFFFFFFFFu, c, o);
        }
        if (lane == 0) { sh[b][wid] = s; sh[b][NWARPS + wid] = c; }
        __syncthreads();   // writes of buffer b visible; buffer b^1 now free
        float S = 0.0f, C = 0.0f;
#pragma unroll
        for (int i = 0; i < NWARPS; i++) { S += sh[b][i]; C += sh[b][NWARPS + i]; }

        if (C < 0.5f) break;              // degenerate guard (shouldn't happen)
        float delta = (S - 1.0f) / C;
        T += delta;
        if (fabsf(delta) < 1e-6f) break;  // uniform across block (S,C identical)
    }

    // ---- Output: relu(z - T). Masked entries are ~-2e7, relu -> 0. ----
#pragma unroll
    for (int v = 0; v < VEC; v++) {
        float4 ov;
        ov.x = fmaxf(0.0f, z[v * 4 + 0] - T);
        ov.y = fmaxf(0.0f, z[v * 4 + 1] - T);
        ov.z = fmaxf(0.0f, z[v * 4 + 2] - T);
        ov.w = fmaxf(0.0f, z[v * 4 + 3] - T);
        orow[t + v * THREADS] = ov;
    }
}

extern "C" void kernel_launch(void* const* d_in, const int* in_sizes, int n_in,
                              void* d_out, int out_size) {
    const float* x = (const float*)d_in[0];
    const float* m = (const float*)d_in[1];
    float* out = (float*)d_out;
    sparsemax_kernel<<<ROWS, THREADS>>>(x, m, out);
}

// round 6
// speedup vs baseline: 1.0624x; 1.0005x over previous
#include <cuda_runtime.h>
#include <cuda_bf16.h>

// Sparsemax over rows: x, mask are [8192, 4096] fp32; out fp32 same shape.
// z = (mask ? x : NEG_BIG) * 2 ; tau solves sum(relu(z - tau)) = 1 (Newton);
// out = relu(z - tau)  (mask multiply implied: masked z is hugely negative).
//
// R6 = R5 (front-batched loads, double-buffered single-barrier Newton)
// with occupancy raised 5 -> 6 CTAs/SM (kernel needs only 40 regs; 6 fit).

#define ROWS 8192
#define COLS 4096
#define THREADS 256
#define NWARPS (THREADS / 32)
#define ELEMS (COLS / THREADS)   // 16 floats per thread
#define VEC (ELEMS / 4)          // 4 float4 per thread

__global__ __launch_bounds__(THREADS, 6)
void sparsemax_kernel(const float* __restrict__ x,
                      const float* __restrict__ m,
                      float* __restrict__ out) {
    const int row = blockIdx.x;
    const int t   = threadIdx.x;
    const int lane = t & 31;
    const int wid  = t >> 5;

    const float4* __restrict__ xr = reinterpret_cast<const float4*>(x + (size_t)row * COLS);
    const float4* __restrict__ mr = reinterpret_cast<const float4*>(m + (size_t)row * COLS);
    float4* __restrict__ orow     = reinterpret_cast<float4*>(out + (size_t)row * COLS);

    // Double-buffered reduction scratch: buffer b holds (s[8], c[8]).
    __shared__ float sh[2][2 * NWARPS];

    // ---- Front-batch ALL loads (8 x LDG.128 in flight per thread) ----
    float4 xv[VEC];
    float4 mv[VEC];
#pragma unroll
    for (int v = 0; v < VEC; v++) xv[v] = xr[t + v * THREADS];
#pragma unroll
    for (int v = 0; v < VEC; v++) mv[v] = mr[t + v * THREADS];

    // ---- Apply mask + temperature, track local max ----
    float z[ELEMS];
    float vmax = -3.0e38f;
    const float NEGZ = -9999999.9f * 2.0f;  // masked value after temperature
#pragma unroll
    for (int v = 0; v < VEC; v++) {
        float z0 = (mv[v].x != 0.0f) ? (xv[v].x * 2.0f) : NEGZ;
        float z1 = (mv[v].y != 0.0f) ? (xv[v].y * 2.0f) : NEGZ;
        float z2 = (mv[v].z != 0.0f) ? (xv[v].z * 2.0f) : NEGZ;
        float z3 = (mv[v].w != 0.0f) ? (xv[v].w * 2.0f) : NEGZ;
        z[v * 4 + 0] = z0;
        z[v * 4 + 1] = z1;
        z[v * 4 + 2] = z2;
        z[v * 4 + 3] = z3;
        vmax = fmaxf(vmax, fmaxf(fmaxf(z0, z1), fmaxf(z2, z3)));
    }

    // ---- Block max reduction (buffer 0; iteration 0 then writes buffer 1,
    //      so no trailing barrier is needed). ----
#pragma unroll
    for (int o = 16; o > 0; o >>= 1)
        vmax = fmaxf(vmax, __shfl_xor_sync(0xFFFFFFFFu, vmax, o));
    if (lane == 0) sh[0][wid] = vmax;
    __syncthreads();
    float zmax = -3.0e38f;
#pragma unroll
    for (int i = 0; i < NWARPS; i++) zmax = fmaxf(zmax, sh[0][i]);

    // ---- Newton on f(T) = sum(relu(z - T)) - 1, from the left ----
    // T0 = zmax - 1 guarantees f(T0) >= 0; Newton from the left is monotone
    // increasing on convex piecewise-linear f and terminates exactly.
    float T = zmax - 1.0f;
#pragma unroll 1
    for (int it = 0; it < 32; ++it) {
        const int b = (it & 1) ^ 1;   // iter 0 -> buffer 1, iter 1 -> buffer 0, ...
        float s = 0.0f, c = 0.0f;
#pragma unroll
        for (int e = 0; e < ELEMS; e++) {
            float d = z[e] - T;
            if (d > 0.0f) { s += d; c += 1.0f; }
        }
#pragma unroll
        for (int o = 16; o > 0; o >>= 1) {
            s += __shfl_xor_sync(0xFFFFFFFFu, s, o);
            c += __shfl_xor_sync(0xFFFFFFFFu, c, o);
        }
        if (lane == 0) { sh[b][wid] = s; sh[b][NWARPS + wid] = c; }
        __syncthreads();   // buffer b visible; buffer b^1 now free
        float S = 0.0f, C = 0.0f;
#pragma unroll
        for (int i = 0; i < NWARPS; i++) { S += sh[b][i]; C += sh[b][NWARPS + i]; }

        if (C < 0.5f) break;              // degenerate guard (shouldn't happen)
        float delta = (S - 1.0f) / C;
        T += delta;
        if (fabsf(delta) < 1e-6f) break;  // uniform across block (S,C identical)
    }

    // ---- Output: relu(z - T). Masked entries are ~-2e7, relu -> 0. ----
#pragma unroll
    for (int v = 0; v < VEC; v++) {
        float4 ov;
        ov.x = fmaxf(0.0f, z[v * 4 + 0] - T);
        ov.y = fmaxf(0.0f, z[v * 4 + 1] - T);
        ov.z = fmaxf(0.0f, z[v * 4 + 2] - T);
        ov.w = fmaxf(0.0f, z[v * 4 + 3] - T);
        orow[t + v * THREADS] = ov;
    }
}

extern "C" void kernel_launch(void* const* d_in, const int* in_sizes, int n_in,
                              void* d_out, int out_size) {
    const float* x = (const float*)d_in[0];
    const float* m = (const float*)d_in[1];
    float* out = (float*)d_out;
    sparsemax_kernel<<<ROWS, THREADS>>>(x, m, out);
}

// round 7
// speedup vs baseline: 1.0662x; 1.0035x over previous
#include <cuda_runtime.h>
#include <cuda_bf16.h>

// Sparsemax over rows: x, mask are [8192, 4096] fp32; out fp32 same shape.
// z = (mask ? x : NEG_BIG) * 2 ; tau solves sum(relu(z - tau)) = 1 (Newton);
// out = relu(z - tau)  (mask multiply implied: masked z is hugely negative).
//
// R7 = R5 (best measured: front-batched loads, double-buffered single-barrier
// Newton, 5 CTAs/SM) + __fdividef on the Newton step (serial critical path).

#define ROWS 8192
#define COLS 4096
#define THREADS 256
#define NWARPS (THREADS / 32)
#define ELEMS (COLS / THREADS)   // 16 floats per thread
#define VEC (ELEMS / 4)          // 4 float4 per thread

__global__ __launch_bounds__(THREADS, 5)
void sparsemax_kernel(const float* __restrict__ x,
                      const float* __restrict__ m,
                      float* __restrict__ out) {
    const int row = blockIdx.x;
    const int t   = threadIdx.x;
    const int lane = t & 31;
    const int wid  = t >> 5;

    const float4* __restrict__ xr = reinterpret_cast<const float4*>(x + (size_t)row * COLS);
    const float4* __restrict__ mr = reinterpret_cast<const float4*>(m + (size_t)row * COLS);
    float4* __restrict__ orow     = reinterpret_cast<float4*>(out + (size_t)row * COLS);

    // Double-buffered reduction scratch: buffer b holds (s[8], c[8]).
    __shared__ float sh[2][2 * NWARPS];

    // ---- Front-batch ALL loads (8 x LDG.128 in flight per thread) ----
    float4 xv[VEC];
    float4 mv[VEC];
#pragma unroll
    for (int v = 0; v < VEC; v++) xv[v] = xr[t + v * THREADS];
#pragma unroll
    for (int v = 0; v < VEC; v++) mv[v] = mr[t + v * THREADS];

    // ---- Apply mask + temperature, track local max ----
    float z[ELEMS];
    float vmax = -3.0e38f;
    const float NEGZ = -9999999.9f * 2.0f;  // masked value after temperature
#pragma unroll
    for (int v = 0; v < VEC; v++) {
        float z0 = (mv[v].x != 0.0f) ? (xv[v].x * 2.0f) : NEGZ;
        float z1 = (mv[v].y != 0.0f) ? (xv[v].y * 2.0f) : NEGZ;
        float z2 = (mv[v].z != 0.0f) ? (xv[v].z * 2.0f) : NEGZ;
        float z3 = (mv[v].w != 0.0f) ? (xv[v].w * 2.0f) : NEGZ;
        z[v * 4 + 0] = z0;
        z[v * 4 + 1] = z1;
        z[v * 4 + 2] = z2;
        z[v * 4 + 3] = z3;
        vmax = fmaxf(vmax, fmaxf(fmaxf(z0, z1), fmaxf(z2, z3)));
    }

    // ---- Block max reduction (buffer 0; iteration 0 then writes buffer 1,
    //      so no trailing barrier is needed). ----
#pragma unroll
    for (int o = 16; o > 0; o >>= 1)
        vmax = fmaxf(vmax, __shfl_xor_sync(0xFFFFFFFFu, vmax, o));
    if (lane == 0) sh[0][wid] = vmax;
    __syncthreads();
    float zmax = -3.0e38f;
#pragma unroll
    for (int i = 0; i < NWARPS; i++) zmax = fmaxf(zmax, sh[0][i]);

    // ---- Newton on f(T) = sum(relu(z - T)) - 1, from the left ----
    // T0 = zmax - 1 guarantees f(T0) >= 0; Newton from the left is monotone
    // increasing on convex piecewise-linear f and terminates exactly.
    float T = zmax - 1.0f;
#pragma unroll 1
    for (int it = 0; it < 32; ++it) {
        const int b = (it & 1) ^ 1;   // iter 0 -> buffer 1, iter 1 -> buffer 0, ...
        float s = 0.0f, c = 0.0f;
#pragma unroll
        for (int e = 0; e < ELEMS; e++) {
            float d = z[e] - T;
            if (d > 0.0f) { s += d; c += 1.0f; }
        }
#pragma unroll
        for (int o = 16; o > 0; o >>= 1) {
            s += __shfl_xor_sync(0xFFFFFFFFu, s, o);
            c += __shfl_xor_sync(0xFFFFFFFFu, c, o);
        }
        if (lane == 0) { sh[b][wid] = s; sh[b][NWARPS + wid] = c; }
        __syncthreads();   // buffer b visible; buffer b^1 now free
        float S = 0.0f, C = 0.0f;
#pragma unroll
        for (int i = 0; i < NWARPS; i++) { S += sh[b][i]; C += sh[b][NWARPS + i]; }

        if (C < 0.5f) break;              // degenerate guard (shouldn't happen)
        float delta = __fdividef(S - 1.0f, C);   // fast path: MUFU.RCP + mul
        T += delta;
        if (fabsf(delta) < 1e-6f) break;  // uniform across block (S,C identical)
    }

    // ---- Output: relu(z - T). Masked entries are ~-2e7, relu -> 0. ----
#pragma unroll
    for (int v = 0; v < VEC; v++) {
        float4 ov;
        ov.x = fmaxf(0.0f, z[v * 4 + 0] - T);
        ov.y = fmaxf(0.0f, z[v * 4 + 1] - T);
        ov.z = fmaxf(0.0f, z[v * 4 + 2] - T);
        ov.w = fmaxf(0.0f, z[v * 4 + 3] - T);
        orow[t + v * THREADS] = ov;
    }
}

extern "C" void kernel_launch(void* const* d_in, const int* in_sizes, int n_in,
                              void* d_out, int out_size) {
    const float* x = (const float*)d_in[0];
    const float* m = (const float*)d_in[1];
    float* out = (float*)d_out;
    sparsemax_kernel<<<ROWS, THREADS>>>(x, m, out);
}